// round 13
// baseline (speedup 1.0000x reference)
#include <cuda_runtime.h>
#include <cuda_fp16.h>
#include <math.h>

namespace {
constexpr int KCODES = 1024;
constexpr int D      = 64;
constexpr int HWSZ   = 64 * 64;
constexpr int NTOK   = 32 * HWSZ;        // 131072
constexpr int TPB    = 256;              // 8 warps, 32 tokens/warp -> 256 tokens/CTA
constexpr int TOKS   = 256;
constexpr int TILE   = 128;              // codes per smem B tile (8 tiles)
constexpr float BIAS   = 32.0f;          // |s| <= 2*||x||*||c|| << 32 -> s+32 > 0
constexpr float MARGIN = 0.045f;         // 0.04 f16-hard + 0.004 key quant @ bias 32
constexpr float RESCUE = 1e-4f;          // fp64 grid-rescue threshold (R2-proven)

constexpr int ASTRIDE_W = 36;            // A row stride in u32 words (144B)
constexpr int SM_A  = 0;                 // 256 * 144B = 36864
constexpr int SM_B  = 36864;             // 128 codes * 128B fragment-packed = 16384
constexpr int SM_CN = 53248;             // 1024 f32 = 4096
constexpr int SM_TOTAL = 57344;          // x4 CTAs = 224 KB <= 228 KB
constexpr int RGRID = 256;
}

__device__ float    g_cnorm[KCODES];
__device__ int      g_counts[KCODES];
__device__ unsigned g_cbf[KCODES * 32];    // f16x2 of (-2c), MMA-fragment-packed
__device__ int      g_nflag;
__device__ int      g_done;
__device__ int      g_ftok[NTOK];
__device__ uint4    g_fcand[NTOK];         // 8 candidate ids: 4 x (u16|u16)

__global__ void vq_nop() {}

// ---- Kernel A: warp-per-code prep: norms + fragment-packed f16(-2c) ----
__global__ void vq_prep(const float* __restrict__ codebook) {
    const int k = (blockIdx.x * blockDim.x + threadIdx.x) >> 5;
    const int w = threadIdx.x & 31;
    if (k >= KCODES) return;
    float a = codebook[k * D + 2 * w];
    float b = codebook[k * D + 2 * w + 1];
    __half2 h = __floats2half2_rn(-2.0f * a, -2.0f * b);
    g_cbf[(k >> 3) * 256 + ((k & 7) * 4 + (w & 3)) * 8 + (w >> 2)] =
        *reinterpret_cast<unsigned*>(&h);
    float p = fmaf(a, a, b * b);
#pragma unroll
    for (int o = 16; o > 0; o >>= 1) p += __shfl_xor_sync(0xffffffffu, p, o);
    if (w == 0) g_cnorm[k] = p;
}

// Biased-positive scores: raw float bits are an order-isomorphic uint key;
// low 10 bits carry the code index so umin() keeps the lowest index on ties.
__device__ __forceinline__ unsigned score_key(float s, int idx) {
    return (__float_as_uint(s) & ~1023u) | (unsigned)idx;   // single LOP3
}
__device__ __forceinline__ void kins2(unsigned kv, unsigned& k0, unsigned& k1) {
    k1 = umin(k1, umax(k0, kv));
    k0 = umin(k0, kv);
}

#define HMMA(c0, c1, c2, c3, a0, a1, a2, a3, b0, b1) \
    asm volatile("mma.sync.aligned.m16n8k16.row.col.f32.f16.f16.f32 " \
        "{%0,%1,%2,%3}, {%4,%5,%6,%7}, {%8,%9}, {%0,%1,%2,%3};" \
        : "+f"(c0), "+f"(c1), "+f"(c2), "+f"(c3) \
        : "r"(a0), "r"(a1), "r"(a2), "r"(a3), "r"(b0), "r"(b1))

// ---- Kernel B: HMMA scoring (2 A-frags/warp) + biased-key top-2, 4 CTAs/SM ----
__global__ __launch_bounds__(TPB, 4) void vq_main(const float* __restrict__ inputs,
                                                  const float* __restrict__ codebook,
                                                  float* __restrict__ out) {
    extern __shared__ char smem[];
    unsigned* Aw = reinterpret_cast<unsigned*>(smem + SM_A);
    float*    cn = reinterpret_cast<float*>(smem + SM_CN);

    const int tid  = threadIdx.x;
    const int wid  = tid >> 5;
    const int lane = tid & 31;
    const int g    = lane >> 2;
    const int q    = lane & 3;
    const int tok_base = blockIdx.x * TOKS;

    {
        const int T = tok_base + tid;
        const int b = T >> 12, hw = T & (HWSZ - 1);
        const float* xin = inputs + (b * D) * HWSZ + hw;
        unsigned* dst = Aw + tid * ASTRIDE_W;
#pragma unroll
        for (int j = 0; j < 32; ++j) {
            __half2 h = __floats2half2_rn(xin[(2 * j) * HWSZ], xin[(2 * j + 1) * HWSZ]);
            dst[j] = *reinterpret_cast<unsigned*>(&h);
        }
        for (int i = tid; i < KCODES; i += TPB) cn[i] = g_cnorm[i] + BIAS;
        const uint4* src = reinterpret_cast<const uint4*>(g_cbf);
        uint4* dstB = reinterpret_cast<uint4*>(smem + SM_B);
        for (int i = tid; i < TILE * 8; i += TPB) dstB[i] = src[i];
    }
    __syncthreads();

    unsigned a[2][4][4];
#pragma unroll
    for (int f = 0; f < 2; ++f) {
        const int r0 = (wid * 32 + f * 16 + g) * ASTRIDE_W;
        const int r1 = (wid * 32 + f * 16 + 8 + g) * ASTRIDE_W;
#pragma unroll
        for (int k = 0; k < 4; ++k) {
            a[f][k][0] = Aw[r0 + k * 8 + q];
            a[f][k][1] = Aw[r1 + k * 8 + q];
            a[f][k][2] = Aw[r0 + k * 8 + q + 4];
            a[f][k][3] = Aw[r1 + k * 8 + q + 4];
        }
    }

    unsigned kA0 = 0xffffffffu, kA1 = 0xffffffffu;
    unsigned kB0 = 0xffffffffu, kB1 = 0xffffffffu;
    unsigned kC0 = 0xffffffffu, kC1 = 0xffffffffu;
    unsigned kD0 = 0xffffffffu, kD1 = 0xffffffffu;

#pragma unroll 1
    for (int tile = 0; tile < 8; ++tile) {
        if (tile > 0) {
            __syncthreads();
            const uint4* src = reinterpret_cast<const uint4*>(g_cbf) + tile * TILE * 8;
            uint4* dstB = reinterpret_cast<uint4*>(smem + SM_B);
            for (int i = tid; i < TILE * 8; i += TPB) dstB[i] = src[i];
            __syncthreads();
        }
        const int tbase = tile * TILE;
#pragma unroll 2
        for (int ch = 0; ch < TILE / 8; ++ch) {
            const uint4* bp = reinterpret_cast<const uint4*>(smem + SM_B)
                              + ch * 64 + lane * 2;
            uint4 lo = bp[0];
            uint4 hi = bp[1];
            const int g0 = tbase + ch * 8 + 2 * q;
            float2 cnv = *reinterpret_cast<const float2*>(&cn[g0]);
            float c0 = cnv.x, c1 = cnv.y, c2 = cnv.x, c3 = cnv.y;
            float c4 = cnv.x, c5 = cnv.y, c6 = cnv.x, c7 = cnv.y;
            HMMA(c0, c1, c2, c3, a[0][0][0], a[0][0][1], a[0][0][2], a[0][0][3], lo.x, lo.y);
            HMMA(c4, c5, c6, c7, a[1][0][0], a[1][0][1], a[1][0][2], a[1][0][3], lo.x, lo.y);
            HMMA(c0, c1, c2, c3, a[0][1][0], a[0][1][1], a[0][1][2], a[0][1][3], lo.z, lo.w);
            HMMA(c4, c5, c6, c7, a[1][1][0], a[1][1][1], a[1][1][2], a[1][1][3], lo.z, lo.w);
            HMMA(c0, c1, c2, c3, a[0][2][0], a[0][2][1], a[0][2][2], a[0][2][3], hi.x, hi.y);
            HMMA(c4, c5, c6, c7, a[1][2][0], a[1][2][1], a[1][2][2], a[1][2][3], hi.x, hi.y);
            HMMA(c0, c1, c2, c3, a[0][3][0], a[0][3][1], a[0][3][2], a[0][3][3], hi.z, hi.w);
            HMMA(c4, c5, c6, c7, a[1][3][0], a[1][3][1], a[1][3][2], a[1][3][3], hi.z, hi.w);
            kins2(score_key(c0, g0),     kA0, kA1);
            kins2(score_key(c1, g0 + 1), kA0, kA1);
            kins2(score_key(c2, g0),     kB0, kB1);
            kins2(score_key(c3, g0 + 1), kB0, kB1);
            kins2(score_key(c4, g0),     kC0, kC1);
            kins2(score_key(c5, g0 + 1), kC0, kC1);
            kins2(score_key(c6, g0),     kD0, kD1);
            kins2(score_key(c7, g0 + 1), kD0, kD1);
        }
    }

#pragma unroll 1
    for (int row = 0; row < 4; ++row) {
        const int T  = tok_base + wid * 32 + row * 8 + g;
        const int b  = T >> 12, hw = T & (HWSZ - 1);
        unsigned lk0 = (row == 0) ? kA0 : (row == 1) ? kB0 : (row == 2) ? kC0 : kD0;
        unsigned lk1 = (row == 0) ? kA1 : (row == 1) ? kB1 : (row == 2) ? kC1 : kD1;
        unsigned m0 = lk0, m1 = lk1;
#pragma unroll
        for (int d = 1; d <= 2; d <<= 1) {
            unsigned r0 = __shfl_xor_sync(0xffffffffu, m0, d);
            unsigned r1 = __shfl_xor_sync(0xffffffffu, m1, d);
            kins2(r0, m0, m1);
            m1 = umin(m1, r1);
        }

        unsigned myc = (lk0 & 1023u) | ((lk1 & 1023u) << 16);
        unsigned qb  = lane & ~3u;
        uint4 fc = make_uint4(__shfl_sync(0xffffffffu, myc, qb + 0),
                              __shfl_sync(0xffffffffu, myc, qb + 1),
                              __shfl_sync(0xffffffffu, myc, qb + 2),
                              __shfl_sync(0xffffffffu, myc, qb + 3));

        if (__uint_as_float(m1) - __uint_as_float(m0) < MARGIN) {
            if (q == 0) {
                int wv = atomicAdd(&g_nflag, 1);
                g_ftok[wv]  = T;
                g_fcand[wv] = fc;
            }
        } else {
            const int bestk = (int)(m0 & 1023u);
            if (q == 0) atomicAdd(&g_counts[bestk], 1);
            const float* xt = inputs + (b * D) * HWSZ + hw;
            const float* qp = codebook + bestk * D;
            float* op = out + (b * D) * HWSZ + hw;
#pragma unroll
            for (int m = 0; m < 16; ++m) {
                int c = q * 16 + m;
                float xv = __ldg(&xt[c * HWSZ]);
                op[c * HWSZ] = xv + (__ldg(&qp[c]) - xv);
            }
        }
    }
}

__device__ __forceinline__ double wsumd(double p) {
#pragma unroll
    for (int o = 16; o > 0; o >>= 1) p += __shfl_xor_sync(0xffffffffu, p, o);
    return p;
}
__device__ __forceinline__ void ins2f(float s, int i, float& e0, int& k0,
                                      float& e1, int& k1) {
    if (s < e0 || (s == e0 && i < k0)) { e1 = e0; k1 = k0; e0 = s; k0 = i; }
    else if (s < e1 || (s == e1 && i < k1)) { e1 = s; k1 = i; }
}

// ---- Kernel C: quad-parallel exact rescue + perplexity + replay-state reset ----
__global__ void vq_rescue_perp(const float* __restrict__ inputs,
                               const float* __restrict__ codebook,
                               float* __restrict__ out, int out_size) {
    const int n    = g_nflag;
    const int gw   = (blockIdx.x * blockDim.x + threadIdx.x) >> 5;
    const int lane = threadIdx.x & 31;
    const int nw   = (gridDim.x * blockDim.x) >> 5;
    const int j    = lane >> 2;          // candidate slot 0..7
    const int qq   = lane & 3;           // 16-dim quarter

    for (int i = gw; i < n; i += nw) {
        const int T = g_ftok[i];
        const uint4 cw = g_fcand[i];
        const unsigned cand2[4] = { cw.x, cw.y, cw.z, cw.w };
        const int k = (int)((cand2[j >> 1] >> ((j & 1) * 16)) & 0xffffu);
        const int b = T >> 12, hw = T & (HWSZ - 1);
        const float* xt = inputs + (b * D) * HWSZ + hw;

        float xs[16];
#pragma unroll
        for (int m = 0; m < 16; ++m) xs[m] = __ldg(&xt[(qq * 16 + m) * HWSZ]);
        const float4* cp = reinterpret_cast<const float4*>(codebook + k * D + qq * 16);
        float d0 = 0.f, d1 = 0.f, d2 = 0.f, d3 = 0.f;
#pragma unroll
        for (int w = 0; w < 4; ++w) {
            float4 cv = __ldg(&cp[w]);
            d0 = fmaf(xs[4 * w + 0], cv.x, d0);
            d1 = fmaf(xs[4 * w + 1], cv.y, d1);
            d2 = fmaf(xs[4 * w + 2], cv.z, d2);
            d3 = fmaf(xs[4 * w + 3], cv.w, d3);
        }
        float part = (d0 + d1) + (d2 + d3);
        part += __shfl_xor_sync(0xffffffffu, part, 1);
        part += __shfl_xor_sync(0xffffffffu, part, 2);
        float e = g_cnorm[k] - 2.0f * part;

        float e0 = e, e1 = 3.4e38f;
        int   k0 = k, k1 = 0x7fffffff;
#pragma unroll
        for (int d = 4; d <= 16; d <<= 1) {
            float re0 = __shfl_xor_sync(0xffffffffu, e0, d);
            float re1 = __shfl_xor_sync(0xffffffffu, e1, d);
            int   rk0 = __shfl_xor_sync(0xffffffffu, k0, d);
            int   rk1 = __shfl_xor_sync(0xffffffffu, k1, d);
            ins2f(re0, rk0, e0, k0, e1, k1);
            ins2f(re1, rk1, e0, k0, e1, k1);
        }

        int bestk = k0;
        float x0 = __ldg(&xt[(2 * lane) * HWSZ]);
        float x1 = __ldg(&xt[(2 * lane + 1) * HWSZ]);
        if (e1 - e0 < RESCUE) {                  // fp64 grid rescue (R2-proven)
            double A = wsumd((double)(x0 * x0) + (double)(x1 * x1));
            float A32 = (float)A;
            int klo = min(k0, k1), khi = max(k0, k1);
            float dsc[2];
#pragma unroll
            for (int jj = 0; jj < 2; ++jj) {
                int kk = jj ? khi : klo;
                float2 cv = *reinterpret_cast<const float2*>(codebook + kk * D + 2 * lane);
                double dot = wsumd((double)x0 * (double)cv.x + (double)x1 * (double)cv.y);
                double C   = wsumd((double)(cv.x * cv.x) + (double)(cv.y * cv.y));
                float t1 = (float)dot;
                float t2 = A32 - 2.0f * t1;
                dsc[jj] = t2 + (float)C;
            }
            bestk = (dsc[1] < dsc[0]) ? khi : klo;
        }
        if (lane == 0) atomicAdd(&g_counts[bestk], 1);
        float2 qv = *reinterpret_cast<const float2*>(codebook + bestk * D + 2 * lane);
        float* op = out + (b * D) * HWSZ + hw;
        op[(2 * lane) * HWSZ]     = x0 + (qv.x - x0);
        op[(2 * lane + 1) * HWSZ] = x1 + (qv.y - x1);
    }

    // Last CTA: perplexity from final counts, then reset replay state.
    __shared__ int sflag;
    __shared__ float red[8];
    __threadfence();
    __syncthreads();
    if (threadIdx.x == 0) sflag = (atomicAdd(&g_done, 1) == gridDim.x - 1);
    __syncthreads();
    if (!sflag) return;
    __threadfence();

    const int t = threadIdx.x;
    float v = 0.f;
#pragma unroll
    for (int jj = 0; jj < 4; ++jj) {
        float e = (float)g_counts[t * 4 + jj] * (1.0f / (float)NTOK);
        v += e * logf(e + 1e-10f);
    }
#pragma unroll
    for (int o = 16; o > 0; o >>= 1) v += __shfl_down_sync(0xffffffffu, v, o);
    if ((t & 31) == 0) red[t >> 5] = v;
    __syncthreads();
    if (t == 0) {
        float s = 0.f;
#pragma unroll
        for (int jj = 0; jj < 8; ++jj) s += red[jj];
        if (out_size > NTOK * D) out[NTOK * D] = expf(-s);
    }
    __syncthreads();
#pragma unroll
    for (int jj = 0; jj < 4; ++jj) g_counts[t * 4 + jj] = 0;
    if (t == 0) { g_nflag = 0; g_done = 0; }
}

extern "C" void kernel_launch(void* const* d_in, const int* in_sizes, int n_in,
                              void* d_out, int out_size) {
    const float* inputs   = (const float*)d_in[0];
    const float* codebook = (const float*)d_in[1];
    float*       out      = (float*)d_out;

    cudaFuncSetAttribute(vq_main, cudaFuncAttributeMaxDynamicSharedMemorySize, SM_TOTAL);

    vq_prep<<<KCODES / 8, TPB>>>(codebook);
    vq_nop<<<1, 1>>>();
    vq_nop<<<1, 1>>>();
    vq_main<<<NTOK / TOKS, TPB, SM_TOTAL>>>(inputs, codebook, out);
    vq_rescue_perp<<<RGRID, TPB>>>(inputs, codebook, out, out_size);
}

// round 14
// speedup vs baseline: 1.0358x; 1.0358x over previous
#include <cuda_runtime.h>
#include <cuda_fp16.h>
#include <math.h>

namespace {
constexpr int KCODES = 1024;
constexpr int D      = 64;
constexpr int HWSZ   = 64 * 64;
constexpr int NTOK   = 32 * HWSZ;        // 131072
constexpr int TPB    = 256;              // 8 warps, 32 tokens/warp -> 256 tokens/CTA
constexpr int TOKS   = 256;
constexpr int TILE   = 256;              // codes per smem B tile (4 tiles)
constexpr float BIAS   = 32.0f;          // |s| <= 2*||x||*||c|| << 32 -> s+32 > 0
constexpr float MARGIN = 0.045f;         // 0.04 f16-hard + 0.004 key quant @ bias 32
constexpr float RESCUE = 1e-4f;          // fp64 grid-rescue threshold (R2-proven)

constexpr int ASTRIDE_W = 36;            // A row stride in u32 words (144B)
// smem union: [0, 36864) stages A (256x144B), then holds B tiles (256x128B=32KB)
constexpr int SM_AB = 0;
constexpr int SM_CN = 36864;             // 1024 f32 = 4096
constexpr int SM_TOTAL = 40960;          // x4 CTAs = 160 KB
constexpr int RGRID = 256;
}

__device__ float    g_cnorm[KCODES];
__device__ int      g_counts[KCODES];
__device__ unsigned g_cbf[KCODES * 32];    // f16x2 of (-2c), MMA-fragment-packed
__device__ int      g_nflag;
__device__ int      g_done;
__device__ int      g_ftok[NTOK];
__device__ uint4    g_fcand[NTOK];         // 8 candidate ids: 4 x (u16|u16)

__global__ void vq_nop() {}

// ---- Kernel A: warp-per-code prep: norms + fragment-packed f16(-2c) ----
__global__ void vq_prep(const float* __restrict__ codebook) {
    const int k = (blockIdx.x * blockDim.x + threadIdx.x) >> 5;
    const int w = threadIdx.x & 31;
    if (k >= KCODES) return;
    float a = codebook[k * D + 2 * w];
    float b = codebook[k * D + 2 * w + 1];
    __half2 h = __floats2half2_rn(-2.0f * a, -2.0f * b);
    g_cbf[(k >> 3) * 256 + ((k & 7) * 4 + (w & 3)) * 8 + (w >> 2)] =
        *reinterpret_cast<unsigned*>(&h);
    float p = fmaf(a, a, b * b);
#pragma unroll
    for (int o = 16; o > 0; o >>= 1) p += __shfl_xor_sync(0xffffffffu, p, o);
    if (w == 0) g_cnorm[k] = p;
}

// Biased-positive scores: raw float bits are an order-isomorphic uint key;
// low 10 bits carry the code index so umin() keeps the lowest index on ties.
__device__ __forceinline__ unsigned score_key(float s, int idx) {
    return (__float_as_uint(s) & ~1023u) | (unsigned)idx;   // single LOP3
}
__device__ __forceinline__ void kins2(unsigned kv, unsigned& k0, unsigned& k1) {
    k1 = umin(k1, umax(k0, kv));
    k0 = umin(k0, kv);
}

#define HMMA(c0, c1, c2, c3, a0, a1, a2, a3, b0, b1) \
    asm volatile("mma.sync.aligned.m16n8k16.row.col.f32.f16.f16.f32 " \
        "{%0,%1,%2,%3}, {%4,%5,%6,%7}, {%8,%9}, {%0,%1,%2,%3};" \
        : "+f"(c0), "+f"(c1), "+f"(c2), "+f"(c3) \
        : "r"(a0), "r"(a1), "r"(a2), "r"(a3), "r"(b0), "r"(b1))

// ---- Kernel B: HMMA scoring, A/B smem union -> 4 CTAs/SM, single wave ----
__global__ __launch_bounds__(TPB, 4) void vq_main(const float* __restrict__ inputs,
                                                  const float* __restrict__ codebook,
                                                  float* __restrict__ out) {
    extern __shared__ char smem[];
    unsigned* Aw = reinterpret_cast<unsigned*>(smem + SM_AB);
    float*    cn = reinterpret_cast<float*>(smem + SM_CN);

    const int tid  = threadIdx.x;
    const int wid  = tid >> 5;
    const int lane = tid & 31;
    const int g    = lane >> 2;
    const int q    = lane & 3;
    const int tok_base = blockIdx.x * TOKS;

    // Stage A into the union region; cn alongside.
    {
        const int T = tok_base + tid;
        const int b = T >> 12, hw = T & (HWSZ - 1);
        const float* xin = inputs + (b * D) * HWSZ + hw;
        unsigned* dst = Aw + tid * ASTRIDE_W;
#pragma unroll
        for (int j = 0; j < 32; ++j) {
            __half2 h = __floats2half2_rn(xin[(2 * j) * HWSZ], xin[(2 * j + 1) * HWSZ]);
            dst[j] = *reinterpret_cast<unsigned*>(&h);
        }
        for (int i = tid; i < KCODES; i += TPB) cn[i] = g_cnorm[i] + BIAS;
    }
    __syncthreads();

    // Extract A fragments to registers, then the region is free for B tiles.
    unsigned a[2][4][4];
#pragma unroll
    for (int f = 0; f < 2; ++f) {
        const int r0 = (wid * 32 + f * 16 + g) * ASTRIDE_W;
        const int r1 = (wid * 32 + f * 16 + 8 + g) * ASTRIDE_W;
#pragma unroll
        for (int k = 0; k < 4; ++k) {
            a[f][k][0] = Aw[r0 + k * 8 + q];
            a[f][k][1] = Aw[r1 + k * 8 + q];
            a[f][k][2] = Aw[r0 + k * 8 + q + 4];
            a[f][k][3] = Aw[r1 + k * 8 + q + 4];
        }
    }
    __syncthreads();

    unsigned kA0 = 0xffffffffu, kA1 = 0xffffffffu;
    unsigned kB0 = 0xffffffffu, kB1 = 0xffffffffu;
    unsigned kC0 = 0xffffffffu, kC1 = 0xffffffffu;
    unsigned kD0 = 0xffffffffu, kD1 = 0xffffffffu;

#pragma unroll 1
    for (int tile = 0; tile < 4; ++tile) {
        {
            const uint4* src = reinterpret_cast<const uint4*>(g_cbf) + tile * TILE * 8;
            uint4* dstB = reinterpret_cast<uint4*>(smem + SM_AB);
            for (int i = tid; i < TILE * 8; i += TPB) dstB[i] = src[i];
        }
        __syncthreads();
        const int tbase = tile * TILE;
#pragma unroll 2
        for (int ch = 0; ch < TILE / 8; ++ch) {
            const uint4* bp = reinterpret_cast<const uint4*>(smem + SM_AB)
                              + ch * 64 + lane * 2;
            uint4 lo = bp[0];
            uint4 hi = bp[1];
            const int g0 = tbase + ch * 8 + 2 * q;
            float2 cnv = *reinterpret_cast<const float2*>(&cn[g0]);
            float c0 = cnv.x, c1 = cnv.y, c2 = cnv.x, c3 = cnv.y;
            float c4 = cnv.x, c5 = cnv.y, c6 = cnv.x, c7 = cnv.y;
            HMMA(c0, c1, c2, c3, a[0][0][0], a[0][0][1], a[0][0][2], a[0][0][3], lo.x, lo.y);
            HMMA(c4, c5, c6, c7, a[1][0][0], a[1][0][1], a[1][0][2], a[1][0][3], lo.x, lo.y);
            HMMA(c0, c1, c2, c3, a[0][1][0], a[0][1][1], a[0][1][2], a[0][1][3], lo.z, lo.w);
            HMMA(c4, c5, c6, c7, a[1][1][0], a[1][1][1], a[1][1][2], a[1][1][3], lo.z, lo.w);
            HMMA(c0, c1, c2, c3, a[0][2][0], a[0][2][1], a[0][2][2], a[0][2][3], hi.x, hi.y);
            HMMA(c4, c5, c6, c7, a[1][2][0], a[1][2][1], a[1][2][2], a[1][2][3], hi.x, hi.y);
            HMMA(c0, c1, c2, c3, a[0][3][0], a[0][3][1], a[0][3][2], a[0][3][3], hi.z, hi.w);
            HMMA(c4, c5, c6, c7, a[1][3][0], a[1][3][1], a[1][3][2], a[1][3][3], hi.z, hi.w);
            kins2(score_key(c0, g0),     kA0, kA1);
            kins2(score_key(c1, g0 + 1), kA0, kA1);
            kins2(score_key(c2, g0),     kB0, kB1);
            kins2(score_key(c3, g0 + 1), kB0, kB1);
            kins2(score_key(c4, g0),     kC0, kC1);
            kins2(score_key(c5, g0 + 1), kC0, kC1);
            kins2(score_key(c6, g0),     kD0, kD1);
            kins2(score_key(c7, g0 + 1), kD0, kD1);
        }
        if (tile < 3) __syncthreads();
    }

#pragma unroll 1
    for (int row = 0; row < 4; ++row) {
        const int T  = tok_base + wid * 32 + row * 8 + g;
        const int b  = T >> 12, hw = T & (HWSZ - 1);
        unsigned lk0 = (row == 0) ? kA0 : (row == 1) ? kB0 : (row == 2) ? kC0 : kD0;
        unsigned lk1 = (row == 0) ? kA1 : (row == 1) ? kB1 : (row == 2) ? kC1 : kD1;
        unsigned m0 = lk0, m1 = lk1;
#pragma unroll
        for (int d = 1; d <= 2; d <<= 1) {
            unsigned r0 = __shfl_xor_sync(0xffffffffu, m0, d);
            unsigned r1 = __shfl_xor_sync(0xffffffffu, m1, d);
            kins2(r0, m0, m1);
            m1 = umin(m1, r1);
        }

        unsigned myc = (lk0 & 1023u) | ((lk1 & 1023u) << 16);
        unsigned qb  = lane & ~3u;
        uint4 fc = make_uint4(__shfl_sync(0xffffffffu, myc, qb + 0),
                              __shfl_sync(0xffffffffu, myc, qb + 1),
                              __shfl_sync(0xffffffffu, myc, qb + 2),
                              __shfl_sync(0xffffffffu, myc, qb + 3));

        if (__uint_as_float(m1) - __uint_as_float(m0) < MARGIN) {
            if (q == 0) {
                int wv = atomicAdd(&g_nflag, 1);
                g_ftok[wv]  = T;
                g_fcand[wv] = fc;
            }
        } else {
            const int bestk = (int)(m0 & 1023u);
            if (q == 0) atomicAdd(&g_counts[bestk], 1);
            const float* xt = inputs + (b * D) * HWSZ + hw;
            const float* qp = codebook + bestk * D;
            float* op = out + (b * D) * HWSZ + hw;
#pragma unroll
            for (int m = 0; m < 16; ++m) {
                int c = q * 16 + m;
                float xv = __ldg(&xt[c * HWSZ]);
                op[c * HWSZ] = xv + (__ldg(&qp[c]) - xv);
            }
        }
    }
}

__device__ __forceinline__ double wsumd(double p) {
#pragma unroll
    for (int o = 16; o > 0; o >>= 1) p += __shfl_xor_sync(0xffffffffu, p, o);
    return p;
}
__device__ __forceinline__ void ins2f(float s, int i, float& e0, int& k0,
                                      float& e1, int& k1) {
    if (s < e0 || (s == e0 && i < k0)) { e1 = e0; k1 = k0; e0 = s; k0 = i; }
    else if (s < e1 || (s == e1 && i < k1)) { e1 = s; k1 = i; }
}

// ---- Kernel C: quad-parallel exact rescue + perplexity + replay-state reset ----
__global__ void vq_rescue_perp(const float* __restrict__ inputs,
                               const float* __restrict__ codebook,
                               float* __restrict__ out, int out_size) {
    const int n    = g_nflag;
    const int gw   = (blockIdx.x * blockDim.x + threadIdx.x) >> 5;
    const int lane = threadIdx.x & 31;
    const int nw   = (gridDim.x * blockDim.x) >> 5;
    const int j    = lane >> 2;          // candidate slot 0..7
    const int qq   = lane & 3;           // 16-dim quarter

    for (int i = gw; i < n; i += nw) {
        const int T = g_ftok[i];
        const uint4 cw = g_fcand[i];
        const unsigned cand2[4] = { cw.x, cw.y, cw.z, cw.w };
        const int k = (int)((cand2[j >> 1] >> ((j & 1) * 16)) & 0xffffu);
        const int b = T >> 12, hw = T & (HWSZ - 1);
        const float* xt = inputs + (b * D) * HWSZ + hw;

        float xs[16];
#pragma unroll
        for (int m = 0; m < 16; ++m) xs[m] = __ldg(&xt[(qq * 16 + m) * HWSZ]);
        const float4* cp = reinterpret_cast<const float4*>(codebook + k * D + qq * 16);
        float d0 = 0.f, d1 = 0.f, d2 = 0.f, d3 = 0.f;
#pragma unroll
        for (int w = 0; w < 4; ++w) {
            float4 cv = __ldg(&cp[w]);
            d0 = fmaf(xs[4 * w + 0], cv.x, d0);
            d1 = fmaf(xs[4 * w + 1], cv.y, d1);
            d2 = fmaf(xs[4 * w + 2], cv.z, d2);
            d3 = fmaf(xs[4 * w + 3], cv.w, d3);
        }
        float part = (d0 + d1) + (d2 + d3);
        part += __shfl_xor_sync(0xffffffffu, part, 1);
        part += __shfl_xor_sync(0xffffffffu, part, 2);
        float e = g_cnorm[k] - 2.0f * part;

        float e0 = e, e1 = 3.4e38f;
        int   k0 = k, k1 = 0x7fffffff;
#pragma unroll
        for (int d = 4; d <= 16; d <<= 1) {
            float re0 = __shfl_xor_sync(0xffffffffu, e0, d);
            float re1 = __shfl_xor_sync(0xffffffffu, e1, d);
            int   rk0 = __shfl_xor_sync(0xffffffffu, k0, d);
            int   rk1 = __shfl_xor_sync(0xffffffffu, k1, d);
            ins2f(re0, rk0, e0, k0, e1, k1);
            ins2f(re1, rk1, e0, k0, e1, k1);
        }

        int bestk = k0;
        float x0 = __ldg(&xt[(2 * lane) * HWSZ]);
        float x1 = __ldg(&xt[(2 * lane + 1) * HWSZ]);
        if (e1 - e0 < RESCUE) {                  // fp64 grid rescue (R2-proven)
            double A = wsumd((double)(x0 * x0) + (double)(x1 * x1));
            float A32 = (float)A;
            int klo = min(k0, k1), khi = max(k0, k1);
            float dsc[2];
#pragma unroll
            for (int jj = 0; jj < 2; ++jj) {
                int kk = jj ? khi : klo;
                float2 cv = *reinterpret_cast<const float2*>(codebook + kk * D + 2 * lane);
                double dot = wsumd((double)x0 * (double)cv.x + (double)x1 * (double)cv.y);
                double C   = wsumd((double)(cv.x * cv.x) + (double)(cv.y * cv.y));
                float t1 = (float)dot;
                float t2 = A32 - 2.0f * t1;
                dsc[jj] = t2 + (float)C;
            }
            bestk = (dsc[1] < dsc[0]) ? khi : klo;
        }
        if (lane == 0) atomicAdd(&g_counts[bestk], 1);
        float2 qv = *reinterpret_cast<const float2*>(codebook + bestk * D + 2 * lane);
        float* op = out + (b * D) * HWSZ + hw;
        op[(2 * lane) * HWSZ]     = x0 + (qv.x - x0);
        op[(2 * lane + 1) * HWSZ] = x1 + (qv.y - x1);
    }

    // Last CTA: perplexity from final counts, then reset replay state.
    __shared__ int sflag;
    __shared__ float red[8];
    __threadfence();
    __syncthreads();
    if (threadIdx.x == 0) sflag = (atomicAdd(&g_done, 1) == gridDim.x - 1);
    __syncthreads();
    if (!sflag) return;
    __threadfence();

    const int t = threadIdx.x;
    float v = 0.f;
#pragma unroll
    for (int jj = 0; jj < 4; ++jj) {
        float e = (float)g_counts[t * 4 + jj] * (1.0f / (float)NTOK);
        v += e * logf(e + 1e-10f);
    }
#pragma unroll
    for (int o = 16; o > 0; o >>= 1) v += __shfl_down_sync(0xffffffffu, v, o);
    if ((t & 31) == 0) red[t >> 5] = v;
    __syncthreads();
    if (t == 0) {
        float s = 0.f;
#pragma unroll
        for (int jj = 0; jj < 8; ++jj) s += red[jj];
        if (out_size > NTOK * D) out[NTOK * D] = expf(-s);
    }
    __syncthreads();
#pragma unroll
    for (int jj = 0; jj < 4; ++jj) g_counts[t * 4 + jj] = 0;
    if (t == 0) { g_nflag = 0; g_done = 0; }
}

extern "C" void kernel_launch(void* const* d_in, const int* in_sizes, int n_in,
                              void* d_out, int out_size) {
    const float* inputs   = (const float*)d_in[0];
    const float* codebook = (const float*)d_in[1];
    float*       out      = (float*)d_out;

    cudaFuncSetAttribute(vq_main, cudaFuncAttributeMaxDynamicSharedMemorySize, SM_TOTAL);

    vq_prep<<<KCODES / 8, TPB>>>(codebook);
    vq_nop<<<1, 1>>>();
    vq_nop<<<1, 1>>>();
    vq_main<<<NTOK / TOKS, TPB, SM_TOTAL>>>(inputs, codebook, out);
    vq_rescue_perp<<<RGRID, TPB>>>(inputs, codebook, out, out_size);
}

// round 15
// speedup vs baseline: 1.0576x; 1.0211x over previous
#include <cuda_runtime.h>
#include <cuda_fp16.h>
#include <math.h>

namespace {
constexpr int KCODES = 1024;
constexpr int D      = 64;
constexpr int HWSZ   = 64 * 64;
constexpr int NTOK   = 32 * HWSZ;        // 131072
constexpr int TPB    = 256;              // 8 warps, 32 tokens/warp -> 256 tokens/CTA
constexpr int TOKS   = 256;
constexpr int TILE   = 128;              // codes per B tile (8 tiles, cp.async ring)
constexpr float BIAS   = 32.0f;          // |s| <= 2*||x||*||c|| << 32 -> s+32 > 0
constexpr float MARGIN = 0.045f;         // 0.04 f16-hard + 0.004 key quant @ bias 32
constexpr float RESCUE = 1e-4f;          // fp64 grid-rescue threshold (R2-proven)

constexpr int ASTRIDE_W = 36;            // A row stride in u32 words (144B)
constexpr int TILE_B   = TILE * 128;     // 16384 bytes per tile
// smem: [0, 49152) = A staging (36864) overlapped by 3-buffer B ring (3x16KB)
constexpr int SM_AB = 0;
constexpr int SM_CN = 49152;             // 1024 f32 = 4096
constexpr int SM_TOTAL = 53248;          // x4 CTAs = 208 KB
constexpr int RGRID = 256;
}

__device__ float    g_cnorm[KCODES];
__device__ int      g_counts[KCODES];
__device__ unsigned g_cbf[KCODES * 32];    // f16x2 of (-2c), MMA-fragment-packed
__device__ int      g_nflag;
__device__ int      g_done;
__device__ int      g_ftok[NTOK];
__device__ uint4    g_fcand[NTOK];         // 8 candidate ids: 4 x (u16|u16)

// ---- Kernel A: warp-per-code prep: norms + fragment-packed f16(-2c) ----
__global__ void vq_prep(const float* __restrict__ codebook) {
    const int k = (blockIdx.x * blockDim.x + threadIdx.x) >> 5;
    const int w = threadIdx.x & 31;
    if (k >= KCODES) return;
    float a = codebook[k * D + 2 * w];
    float b = codebook[k * D + 2 * w + 1];
    __half2 h = __floats2half2_rn(-2.0f * a, -2.0f * b);
    g_cbf[(k >> 3) * 256 + ((k & 7) * 4 + (w & 3)) * 8 + (w >> 2)] =
        *reinterpret_cast<unsigned*>(&h);
    float p = fmaf(a, a, b * b);
#pragma unroll
    for (int o = 16; o > 0; o >>= 1) p += __shfl_xor_sync(0xffffffffu, p, o);
    if (w == 0) g_cnorm[k] = p;
}

__device__ __forceinline__ unsigned smem_u32(const void* p) {
    unsigned a;
    asm("{ .reg .u64 t; cvta.to.shared.u64 t, %1; cvt.u32.u64 %0, t; }" : "=r"(a) : "l"(p));
    return a;
}

// Biased-positive scores: raw float bits are an order-isomorphic uint key;
// low 10 bits carry the code index so umin() keeps the lowest index on ties.
__device__ __forceinline__ unsigned score_key(float s, int idx) {
    return (__float_as_uint(s) & ~1023u) | (unsigned)idx;   // single LOP3
}
__device__ __forceinline__ void kins2(unsigned kv, unsigned& k0, unsigned& k1) {
    k1 = umin(k1, umax(k0, kv));
    k0 = umin(k0, kv);
}

#define HMMA(c0, c1, c2, c3, a0, a1, a2, a3, b0, b1) \
    asm volatile("mma.sync.aligned.m16n8k16.row.col.f32.f16.f16.f32 " \
        "{%0,%1,%2,%3}, {%4,%5,%6,%7}, {%8,%9}, {%0,%1,%2,%3};" \
        : "+f"(c0), "+f"(c1), "+f"(c2), "+f"(c3) \
        : "r"(a0), "r"(a1), "r"(a2), "r"(a3), "r"(b0), "r"(b1))

#define CP_ASYNC16(saddr, gptr) \
    asm volatile("cp.async.cg.shared.global [%0], [%1], 16;" \
        :: "r"(saddr), "l"(gptr) : "memory")
#define CP_COMMIT()  asm volatile("cp.async.commit_group;" ::: "memory")
#define CP_WAIT1()   asm volatile("cp.async.wait_group 1;" ::: "memory")

// ---- Kernel B: HMMA scoring, cp.async 3-buffer B ring, 4 CTAs/SM ----
__global__ __launch_bounds__(TPB, 4) void vq_main(const float* __restrict__ inputs,
                                                  const float* __restrict__ codebook,
                                                  float* __restrict__ out) {
    extern __shared__ char smem[];
    unsigned* Aw = reinterpret_cast<unsigned*>(smem + SM_AB);
    float*    cn = reinterpret_cast<float*>(smem + SM_CN);
    const unsigned sb = smem_u32(smem);

    const int tid  = threadIdx.x;
    const int wid  = tid >> 5;
    const int lane = tid & 31;
    const int g    = lane >> 2;
    const int q    = lane & 3;
    const int tok_base = blockIdx.x * TOKS;

    // Stage A into the (to-be-reused) region; cn alongside.
    {
        const int T = tok_base + tid;
        const int b = T >> 12, hw = T & (HWSZ - 1);
        const float* xin = inputs + (b * D) * HWSZ + hw;
        unsigned* dst = Aw + tid * ASTRIDE_W;
#pragma unroll
        for (int j = 0; j < 32; ++j) {
            __half2 h = __floats2half2_rn(xin[(2 * j) * HWSZ], xin[(2 * j + 1) * HWSZ]);
            dst[j] = *reinterpret_cast<unsigned*>(&h);
        }
        for (int i = tid; i < KCODES; i += TPB) cn[i] = g_cnorm[i] + BIAS;
    }
    __syncthreads();

    // Extract A fragments; after the next barrier the region becomes the B ring.
    unsigned a[2][4][4];
#pragma unroll
    for (int f = 0; f < 2; ++f) {
        const int r0 = (wid * 32 + f * 16 + g) * ASTRIDE_W;
        const int r1 = (wid * 32 + f * 16 + 8 + g) * ASTRIDE_W;
#pragma unroll
        for (int k = 0; k < 4; ++k) {
            a[f][k][0] = Aw[r0 + k * 8 + q];
            a[f][k][1] = Aw[r1 + k * 8 + q];
            a[f][k][2] = Aw[r0 + k * 8 + q + 4];
            a[f][k][3] = Aw[r1 + k * 8 + q + 4];
        }
    }
    __syncthreads();

    // Prime the cp.async pipeline: tiles 0 and 1.
#pragma unroll
    for (int t = 0; t < 2; ++t) {
        const char* src = reinterpret_cast<const char*>(g_cbf) + t * TILE_B;
        unsigned dst = sb + t * TILE_B;
#pragma unroll
        for (int i = 0; i < TILE_B / 16 / TPB; ++i) {   // 4 x 16B per thread
            int o = (i * TPB + tid) * 16;
            CP_ASYNC16(dst + o, src + o);
        }
        CP_COMMIT();
    }

    unsigned kA0 = 0xffffffffu, kA1 = 0xffffffffu;
    unsigned kB0 = 0xffffffffu, kB1 = 0xffffffffu;
    unsigned kC0 = 0xffffffffu, kC1 = 0xffffffffu;
    unsigned kD0 = 0xffffffffu, kD1 = 0xffffffffu;

#pragma unroll 1
    for (int tile = 0; tile < 8; ++tile) {
        CP_WAIT1();            // tile's group complete (<=1 pending = tile+1)
        __syncthreads();       // also certifies all warps finished tile-1
        if (tile + 2 < 8) {    // safe: (tile+2)%3 buffer was tile-1's
            const char* src = reinterpret_cast<const char*>(g_cbf) + (tile + 2) * TILE_B;
            unsigned dst = sb + ((tile + 2) % 3) * TILE_B;
#pragma unroll
            for (int i = 0; i < TILE_B / 16 / TPB; ++i) {
                int o = (i * TPB + tid) * 16;
                CP_ASYNC16(dst + o, src + o);
            }
            CP_COMMIT();
        } else {
            CP_COMMIT();       // keep group count aligned for CP_WAIT1
        }
        const uint4* bufB = reinterpret_cast<const uint4*>(smem + (tile % 3) * TILE_B);
        const int tbase = tile * TILE;
#pragma unroll 2
        for (int ch = 0; ch < TILE / 8; ++ch) {
            const uint4* bp = bufB + ch * 64 + lane * 2;
            uint4 lo = bp[0];
            uint4 hi = bp[1];
            const int g0 = tbase + ch * 8 + 2 * q;
            float2 cnv = *reinterpret_cast<const float2*>(&cn[g0]);
            float c0 = cnv.x, c1 = cnv.y, c2 = cnv.x, c3 = cnv.y;
            float c4 = cnv.x, c5 = cnv.y, c6 = cnv.x, c7 = cnv.y;
            HMMA(c0, c1, c2, c3, a[0][0][0], a[0][0][1], a[0][0][2], a[0][0][3], lo.x, lo.y);
            HMMA(c4, c5, c6, c7, a[1][0][0], a[1][0][1], a[1][0][2], a[1][0][3], lo.x, lo.y);
            HMMA(c0, c1, c2, c3, a[0][1][0], a[0][1][1], a[0][1][2], a[0][1][3], lo.z, lo.w);
            HMMA(c4, c5, c6, c7, a[1][1][0], a[1][1][1], a[1][1][2], a[1][1][3], lo.z, lo.w);
            HMMA(c0, c1, c2, c3, a[0][2][0], a[0][2][1], a[0][2][2], a[0][2][3], hi.x, hi.y);
            HMMA(c4, c5, c6, c7, a[1][2][0], a[1][2][1], a[1][2][2], a[1][2][3], hi.x, hi.y);
            HMMA(c0, c1, c2, c3, a[0][3][0], a[0][3][1], a[0][3][2], a[0][3][3], hi.z, hi.w);
            HMMA(c4, c5, c6, c7, a[1][3][0], a[1][3][1], a[1][3][2], a[1][3][3], hi.z, hi.w);
            kins2(score_key(c0, g0),     kA0, kA1);
            kins2(score_key(c1, g0 + 1), kA0, kA1);
            kins2(score_key(c2, g0),     kB0, kB1);
            kins2(score_key(c3, g0 + 1), kB0, kB1);
            kins2(score_key(c4, g0),     kC0, kC1);
            kins2(score_key(c5, g0 + 1), kC0, kC1);
            kins2(score_key(c6, g0),     kD0, kD1);
            kins2(score_key(c7, g0 + 1), kD0, kD1);
        }
    }

#pragma unroll 1
    for (int row = 0; row < 4; ++row) {
        const int T  = tok_base + wid * 32 + row * 8 + g;
        const int b  = T >> 12, hw = T & (HWSZ - 1);
        unsigned lk0 = (row == 0) ? kA0 : (row == 1) ? kB0 : (row == 2) ? kC0 : kD0;
        unsigned lk1 = (row == 0) ? kA1 : (row == 1) ? kB1 : (row == 2) ? kC1 : kD1;
        unsigned m0 = lk0, m1 = lk1;
#pragma unroll
        for (int d = 1; d <= 2; d <<= 1) {
            unsigned r0 = __shfl_xor_sync(0xffffffffu, m0, d);
            unsigned r1 = __shfl_xor_sync(0xffffffffu, m1, d);
            kins2(r0, m0, m1);
            m1 = umin(m1, r1);
        }

        unsigned myc = (lk0 & 1023u) | ((lk1 & 1023u) << 16);
        unsigned qb  = lane & ~3u;
        uint4 fc = make_uint4(__shfl_sync(0xffffffffu, myc, qb + 0),
                              __shfl_sync(0xffffffffu, myc, qb + 1),
                              __shfl_sync(0xffffffffu, myc, qb + 2),
                              __shfl_sync(0xffffffffu, myc, qb + 3));

        if (__uint_as_float(m1) - __uint_as_float(m0) < MARGIN) {
            if (q == 0) {
                int wv = atomicAdd(&g_nflag, 1);
                g_ftok[wv]  = T;
                g_fcand[wv] = fc;
            }
        } else {
            const int bestk = (int)(m0 & 1023u);
            if (q == 0) atomicAdd(&g_counts[bestk], 1);
            const float* xt = inputs + (b * D) * HWSZ + hw;
            const float* qp = codebook + bestk * D;
            float* op = out + (b * D) * HWSZ + hw;
#pragma unroll
            for (int m = 0; m < 16; ++m) {
                int c = q * 16 + m;
                float xv = __ldg(&xt[c * HWSZ]);
                op[c * HWSZ] = xv + (__ldg(&qp[c]) - xv);
            }
        }
    }
}

__device__ __forceinline__ double wsumd(double p) {
#pragma unroll
    for (int o = 16; o > 0; o >>= 1) p += __shfl_xor_sync(0xffffffffu, p, o);
    return p;
}
__device__ __forceinline__ void ins2f(float s, int i, float& e0, int& k0,
                                      float& e1, int& k1) {
    if (s < e0 || (s == e0 && i < k0)) { e1 = e0; k1 = k0; e0 = s; k0 = i; }
    else if (s < e1 || (s == e1 && i < k1)) { e1 = s; k1 = i; }
}

// ---- Kernel C: quad-parallel exact rescue + perplexity + replay-state reset ----
__global__ void vq_rescue_perp(const float* __restrict__ inputs,
                               const float* __restrict__ codebook,
                               float* __restrict__ out, int out_size) {
    const int n    = g_nflag;
    const int gw   = (blockIdx.x * blockDim.x + threadIdx.x) >> 5;
    const int lane = threadIdx.x & 31;
    const int nw   = (gridDim.x * blockDim.x) >> 5;
    const int j    = lane >> 2;          // candidate slot 0..7
    const int qq   = lane & 3;           // 16-dim quarter

    for (int i = gw; i < n; i += nw) {
        const int T = g_ftok[i];
        const uint4 cw = g_fcand[i];
        const unsigned cand2[4] = { cw.x, cw.y, cw.z, cw.w };
        const int k = (int)((cand2[j >> 1] >> ((j & 1) * 16)) & 0xffffu);
        const int b = T >> 12, hw = T & (HWSZ - 1);
        const float* xt = inputs + (b * D) * HWSZ + hw;

        float xs[16];
#pragma unroll
        for (int m = 0; m < 16; ++m) xs[m] = __ldg(&xt[(qq * 16 + m) * HWSZ]);
        const float4* cp = reinterpret_cast<const float4*>(codebook + k * D + qq * 16);
        float d0 = 0.f, d1 = 0.f, d2 = 0.f, d3 = 0.f;
#pragma unroll
        for (int w = 0; w < 4; ++w) {
            float4 cv = __ldg(&cp[w]);
            d0 = fmaf(xs[4 * w + 0], cv.x, d0);
            d1 = fmaf(xs[4 * w + 1], cv.y, d1);
            d2 = fmaf(xs[4 * w + 2], cv.z, d2);
            d3 = fmaf(xs[4 * w + 3], cv.w, d3);
        }
        float part = (d0 + d1) + (d2 + d3);
        part += __shfl_xor_sync(0xffffffffu, part, 1);
        part += __shfl_xor_sync(0xffffffffu, part, 2);
        float e = g_cnorm[k] - 2.0f * part;

        float e0 = e, e1 = 3.4e38f;
        int   k0 = k, k1 = 0x7fffffff;
#pragma unroll
        for (int d = 4; d <= 16; d <<= 1) {
            float re0 = __shfl_xor_sync(0xffffffffu, e0, d);
            float re1 = __shfl_xor_sync(0xffffffffu, e1, d);
            int   rk0 = __shfl_xor_sync(0xffffffffu, k0, d);
            int   rk1 = __shfl_xor_sync(0xffffffffu, k1, d);
            ins2f(re0, rk0, e0, k0, e1, k1);
            ins2f(re1, rk1, e0, k0, e1, k1);
        }

        int bestk = k0;
        float x0 = __ldg(&xt[(2 * lane) * HWSZ]);
        float x1 = __ldg(&xt[(2 * lane + 1) * HWSZ]);
        if (e1 - e0 < RESCUE) {                  // fp64 grid rescue (R2-proven)
            double A = wsumd((double)(x0 * x0) + (double)(x1 * x1));
            float A32 = (float)A;
            int klo = min(k0, k1), khi = max(k0, k1);
            float dsc[2];
#pragma unroll
            for (int jj = 0; jj < 2; ++jj) {
                int kk = jj ? khi : klo;
                float2 cv = *reinterpret_cast<const float2*>(codebook + kk * D + 2 * lane);
                double dot = wsumd((double)x0 * (double)cv.x + (double)x1 * (double)cv.y);
                double C   = wsumd((double)(cv.x * cv.x) + (double)(cv.y * cv.y));
                float t1 = (float)dot;
                float t2 = A32 - 2.0f * t1;
                dsc[jj] = t2 + (float)C;
            }
            bestk = (dsc[1] < dsc[0]) ? khi : klo;
        }
        if (lane == 0) atomicAdd(&g_counts[bestk], 1);
        float2 qv = *reinterpret_cast<const float2*>(codebook + bestk * D + 2 * lane);
        float* op = out + (b * D) * HWSZ + hw;
        op[(2 * lane) * HWSZ]     = x0 + (qv.x - x0);
        op[(2 * lane + 1) * HWSZ] = x1 + (qv.y - x1);
    }

    // Last CTA: perplexity from final counts, then reset replay state.
    __shared__ int sflag;
    __shared__ float red[8];
    __threadfence();
    __syncthreads();
    if (threadIdx.x == 0) sflag = (atomicAdd(&g_done, 1) == gridDim.x - 1);
    __syncthreads();
    if (!sflag) return;
    __threadfence();

    const int t = threadIdx.x;
    float v = 0.f;
#pragma unroll
    for (int jj = 0; jj < 4; ++jj) {
        float e = (float)g_counts[t * 4 + jj] * (1.0f / (float)NTOK);
        v += e * logf(e + 1e-10f);
    }
#pragma unroll
    for (int o = 16; o > 0; o >>= 1) v += __shfl_down_sync(0xffffffffu, v, o);
    if ((t & 31) == 0) red[t >> 5] = v;
    __syncthreads();
    if (t == 0) {
        float s = 0.f;
#pragma unroll
        for (int jj = 0; jj < 8; ++jj) s += red[jj];
        if (out_size > NTOK * D) out[NTOK * D] = expf(-s);
    }
    __syncthreads();
#pragma unroll
    for (int jj = 0; jj < 4; ++jj) g_counts[t * 4 + jj] = 0;
    if (t == 0) { g_nflag = 0; g_done = 0; }
}

extern "C" void kernel_launch(void* const* d_in, const int* in_sizes, int n_in,
                              void* d_out, int out_size) {
    const float* inputs   = (const float*)d_in[0];
    const float* codebook = (const float*)d_in[1];
    float*       out      = (float*)d_out;

    cudaFuncSetAttribute(vq_main, cudaFuncAttributeMaxDynamicSharedMemorySize, SM_TOTAL);

    vq_prep<<<KCODES / 8, TPB>>>(codebook);
    vq_main<<<NTOK / TOKS, TPB, SM_TOTAL>>>(inputs, codebook, out);
    vq_rescue_perp<<<RGRID, TPB>>>(inputs, codebook, out, out_size);
}

// round 17
// speedup vs baseline: 1.1570x; 1.0939x over previous
#include <cuda_runtime.h>
#include <cuda_fp16.h>
#include <math.h>

namespace {
constexpr int KCODES = 1024;
constexpr int D      = 64;
constexpr int HWSZ   = 64 * 64;
constexpr int NTOK   = 32 * HWSZ;        // 131072
constexpr int TPB    = 256;              // 8 warps, 32 tokens/warp -> 256 tokens/CTA
constexpr int TOKS   = 256;
constexpr int TILE   = 128;              // codes per B tile (8 tiles, cp.async ring)
constexpr float BIAS   = 32.0f;          // |s| <= 2*||x||*||c|| << 32 -> s+32 > 0
constexpr float MARGIN = 0.045f;         // 0.04 f16-hard + 0.004 key quant @ bias 32
constexpr float RESCUE = 1e-4f;          // fp64 grid-rescue threshold (R2-proven)

constexpr int ASTRIDE_W = 36;            // A row stride in u32 words (144B)
constexpr int TILE_B   = TILE * 128;     // 16384 bytes per tile
constexpr int SM_AB = 0;                 // A staging (36864) / 3-buffer B ring (3x16KB)
constexpr int SM_CN = 49152;             // 1024 f32 = 4096
constexpr int SM_TOTAL = 53248;          // x4 CTAs = 208 KB
constexpr int RGRID = 256;
}

__device__ float    g_cnorm[KCODES];
__device__ int      g_counts[KCODES];
__device__ unsigned g_cbf[KCODES * 32];    // f16x2 of (-2c), MMA-fragment-packed
__device__ int      g_nflag;
__device__ int      g_done;
__device__ int      g_ftok[NTOK];
__device__ uint4    g_fcand[NTOK];         // 8 candidate ids: 4 x (u16|u16)

// ---- Kernel A: warp-per-code prep: norms + fragment-packed f16(-2c) ----
__global__ void vq_prep(const float* __restrict__ codebook) {
    const int k = (blockIdx.x * blockDim.x + threadIdx.x) >> 5;
    const int w = threadIdx.x & 31;
    if (k >= KCODES) return;
    float a = codebook[k * D + 2 * w];
    float b = codebook[k * D + 2 * w + 1];
    __half2 h = __floats2half2_rn(-2.0f * a, -2.0f * b);
    g_cbf[(k >> 3) * 256 + ((k & 7) * 4 + (w & 3)) * 8 + (w >> 2)] =
        *reinterpret_cast<unsigned*>(&h);
    float p = fmaf(a, a, b * b);
#pragma unroll
    for (int o = 16; o > 0; o >>= 1) p += __shfl_xor_sync(0xffffffffu, p, o);
    if (w == 0) g_cnorm[k] = p;
}

__device__ __forceinline__ unsigned smem_u32(const void* p) {
    unsigned a;
    asm("{ .reg .u64 t; cvta.to.shared.u64 t, %1; cvt.u32.u64 %0, t; }" : "=r"(a) : "l"(p));
    return a;
}

// Biased-positive scores: raw float bits are an order-isomorphic uint key;
// low 10 bits carry the code index so umin() keeps the lowest index on ties.
__device__ __forceinline__ unsigned score_key(float s, int idx) {
    return (__float_as_uint(s) & ~1023u) | (unsigned)idx;   // single LOP3
}
__device__ __forceinline__ void kins2(unsigned kv, unsigned& k0, unsigned& k1) {
    k1 = umin(k1, umax(k0, kv));
    k0 = umin(k0, kv);
}

#define HMMA(c0, c1, c2, c3, a0, a1, a2, a3, b0, b1) \
    asm volatile("mma.sync.aligned.m16n8k16.row.col.f32.f16.f16.f32 " \
        "{%0,%1,%2,%3}, {%4,%5,%6,%7}, {%8,%9}, {%0,%1,%2,%3};" \
        : "+f"(c0), "+f"(c1), "+f"(c2), "+f"(c3) \
        : "r"(a0), "r"(a1), "r"(a2), "r"(a3), "r"(b0), "r"(b1))

#define CP_ASYNC16(saddr, gptr) \
    asm volatile("cp.async.cg.shared.global [%0], [%1], 16;" \
        :: "r"(saddr), "l"(gptr) : "memory")
#define CP_COMMIT()  asm volatile("cp.async.commit_group;" ::: "memory")
#define CP_WAIT1()   asm volatile("cp.async.wait_group 1;" ::: "memory")

// ---- Kernel B: HMMA scoring (R15 mainloop) + lane-transposed coalesced epilogue ----
__global__ __launch_bounds__(TPB, 4) void vq_main(const float* __restrict__ inputs,
                                                  const float* __restrict__ codebook,
                                                  float* __restrict__ out) {
    extern __shared__ char smem[];
    unsigned* Aw = reinterpret_cast<unsigned*>(smem + SM_AB);
    float*    cn = reinterpret_cast<float*>(smem + SM_CN);
    const unsigned sb = smem_u32(smem);

    const int tid  = threadIdx.x;
    const int wid  = tid >> 5;
    const int lane = tid & 31;
    const int g    = lane >> 2;
    const int q    = lane & 3;
    const int tok_base = blockIdx.x * TOKS;

    // Stage A into the (to-be-reused) region; cn alongside.
    {
        const int T = tok_base + tid;
        const int b = T >> 12, hw = T & (HWSZ - 1);
        const float* xin = inputs + (b * D) * HWSZ + hw;
        unsigned* dst = Aw + tid * ASTRIDE_W;
#pragma unroll
        for (int j = 0; j < 32; ++j) {
            __half2 h = __floats2half2_rn(xin[(2 * j) * HWSZ], xin[(2 * j + 1) * HWSZ]);
            dst[j] = *reinterpret_cast<unsigned*>(&h);
        }
        for (int i = tid; i < KCODES; i += TPB) cn[i] = g_cnorm[i] + BIAS;
    }
    __syncthreads();

    unsigned a[2][4][4];
#pragma unroll
    for (int f = 0; f < 2; ++f) {
        const int r0 = (wid * 32 + f * 16 + g) * ASTRIDE_W;
        const int r1 = (wid * 32 + f * 16 + 8 + g) * ASTRIDE_W;
#pragma unroll
        for (int k = 0; k < 4; ++k) {
            a[f][k][0] = Aw[r0 + k * 8 + q];
            a[f][k][1] = Aw[r1 + k * 8 + q];
            a[f][k][2] = Aw[r0 + k * 8 + q + 4];
            a[f][k][3] = Aw[r1 + k * 8 + q + 4];
        }
    }
    __syncthreads();

    // Prime the cp.async pipeline: tiles 0 and 1.
#pragma unroll
    for (int t = 0; t < 2; ++t) {
        const char* src = reinterpret_cast<const char*>(g_cbf) + t * TILE_B;
        unsigned dst = sb + t * TILE_B;
#pragma unroll
        for (int i = 0; i < TILE_B / 16 / TPB; ++i) {
            int o = (i * TPB + tid) * 16;
            CP_ASYNC16(dst + o, src + o);
        }
        CP_COMMIT();
    }

    unsigned kA0 = 0xffffffffu, kA1 = 0xffffffffu;
    unsigned kB0 = 0xffffffffu, kB1 = 0xffffffffu;
    unsigned kC0 = 0xffffffffu, kC1 = 0xffffffffu;
    unsigned kD0 = 0xffffffffu, kD1 = 0xffffffffu;

#pragma unroll 1
    for (int tile = 0; tile < 8; ++tile) {
        CP_WAIT1();
        __syncthreads();
        if (tile + 2 < 8) {
            const char* src = reinterpret_cast<const char*>(g_cbf) + (tile + 2) * TILE_B;
            unsigned dst = sb + ((tile + 2) % 3) * TILE_B;
#pragma unroll
            for (int i = 0; i < TILE_B / 16 / TPB; ++i) {
                int o = (i * TPB + tid) * 16;
                CP_ASYNC16(dst + o, src + o);
            }
            CP_COMMIT();
        } else {
            CP_COMMIT();
        }
        const uint4* bufB = reinterpret_cast<const uint4*>(smem + (tile % 3) * TILE_B);
        const int tbase = tile * TILE;
#pragma unroll 2
        for (int ch = 0; ch < TILE / 8; ++ch) {
            const uint4* bp = bufB + ch * 64 + lane * 2;
            uint4 lo = bp[0];
            uint4 hi = bp[1];
            const int g0 = tbase + ch * 8 + 2 * q;
            float2 cnv = *reinterpret_cast<const float2*>(&cn[g0]);
            float c0 = cnv.x, c1 = cnv.y, c2 = cnv.x, c3 = cnv.y;
            float c4 = cnv.x, c5 = cnv.y, c6 = cnv.x, c7 = cnv.y;
            HMMA(c0, c1, c2, c3, a[0][0][0], a[0][0][1], a[0][0][2], a[0][0][3], lo.x, lo.y);
            HMMA(c4, c5, c6, c7, a[1][0][0], a[1][0][1], a[1][0][2], a[1][0][3], lo.x, lo.y);
            HMMA(c0, c1, c2, c3, a[0][1][0], a[0][1][1], a[0][1][2], a[0][1][3], lo.z, lo.w);
            HMMA(c4, c5, c6, c7, a[1][1][0], a[1][1][1], a[1][1][2], a[1][1][3], lo.z, lo.w);
            HMMA(c0, c1, c2, c3, a[0][2][0], a[0][2][1], a[0][2][2], a[0][2][3], hi.x, hi.y);
            HMMA(c4, c5, c6, c7, a[1][2][0], a[1][2][1], a[1][2][2], a[1][2][3], hi.x, hi.y);
            HMMA(c0, c1, c2, c3, a[0][3][0], a[0][3][1], a[0][3][2], a[0][3][3], hi.z, hi.w);
            HMMA(c4, c5, c6, c7, a[1][3][0], a[1][3][1], a[1][3][2], a[1][3][3], hi.z, hi.w);
            kins2(score_key(c0, g0),     kA0, kA1);
            kins2(score_key(c1, g0 + 1), kA0, kA1);
            kins2(score_key(c2, g0),     kB0, kB1);
            kins2(score_key(c3, g0 + 1), kB0, kB1);
            kins2(score_key(c4, g0),     kC0, kC1);
            kins2(score_key(c5, g0 + 1), kC0, kC1);
            kins2(score_key(c6, g0),     kD0, kD1);
            kins2(score_key(c7, g0 + 1), kD0, kD1);
        }
    }

    // Selection rows: merge per-quad, flag/histogram, and transpose winners so
    // lane L ends up owning token tok_base + wid*32 + L.
    unsigned mykey = 0;                        // bestk | (flag<<15)
#pragma unroll
    for (int row = 0; row < 4; ++row) {
        const int T  = tok_base + wid * 32 + row * 8 + g;
        unsigned lk0 = (row == 0) ? kA0 : (row == 1) ? kB0 : (row == 2) ? kC0 : kD0;
        unsigned lk1 = (row == 0) ? kA1 : (row == 1) ? kB1 : (row == 2) ? kC1 : kD1;
        unsigned m0 = lk0, m1 = lk1;
#pragma unroll
        for (int d = 1; d <= 2; d <<= 1) {
            unsigned r0 = __shfl_xor_sync(0xffffffffu, m0, d);
            unsigned r1 = __shfl_xor_sync(0xffffffffu, m1, d);
            kins2(r0, m0, m1);
            m1 = umin(m1, r1);
        }

        unsigned myc = (lk0 & 1023u) | ((lk1 & 1023u) << 16);
        unsigned qb  = lane & ~3u;
        uint4 fc = make_uint4(__shfl_sync(0xffffffffu, myc, qb + 0),
                              __shfl_sync(0xffffffffu, myc, qb + 1),
                              __shfl_sync(0xffffffffu, myc, qb + 2),
                              __shfl_sync(0xffffffffu, myc, qb + 3));

        const bool flag = (__uint_as_float(m1) - __uint_as_float(m0) < MARGIN);
        if (flag) {
            if (q == 0) {
                int wv = atomicAdd(&g_nflag, 1);
                g_ftok[wv]  = T;
                g_fcand[wv] = fc;
            }
        } else {
            if (q == 0) atomicAdd(&g_counts[m0 & 1023u], 1);
        }
        unsigned wk = (m0 & 1023u) | (flag ? 32768u : 0u);
        unsigned v = __shfl_sync(0xffffffffu, wk, (lane & 7) << 2);
        if ((lane >> 3) == row) mykey = v;
    }

    // Coalesced per-lane epilogue: lane L writes token tok_base + wid*32 + L.
    if (!(mykey & 32768u)) {
        const int T  = tok_base + wid * 32 + lane;
        const int b  = T >> 12, hw = T & (HWSZ - 1);
        const int bestk = (int)(mykey & 1023u);
        const float*  xt = inputs + (b * D) * HWSZ + hw;
        const float4* cp = reinterpret_cast<const float4*>(codebook + bestk * D);
        float* op = out + (b * D) * HWSZ + hw;
#pragma unroll
        for (int w = 0; w < 16; ++w) {
            float4 qv = __ldg(&cp[w]);
            int c = w * 4;
            float x0 = __ldg(&xt[(c + 0) * HWSZ]);
            float x1 = __ldg(&xt[(c + 1) * HWSZ]);
            float x2 = __ldg(&xt[(c + 2) * HWSZ]);
            float x3 = __ldg(&xt[(c + 3) * HWSZ]);
            op[(c + 0) * HWSZ] = x0 + (qv.x - x0);
            op[(c + 1) * HWSZ] = x1 + (qv.y - x1);
            op[(c + 2) * HWSZ] = x2 + (qv.z - x2);
            op[(c + 3) * HWSZ] = x3 + (qv.w - x3);
        }
    }
}

__device__ __forceinline__ double wsumd(double p) {
#pragma unroll
    for (int o = 16; o > 0; o >>= 1) p += __shfl_xor_sync(0xffffffffu, p, o);
    return p;
}
__device__ __forceinline__ void ins2f(float s, int i, float& e0, int& k0,
                                      float& e1, int& k1) {
    if (s < e0 || (s == e0 && i < k0)) { e1 = e0; k1 = k0; e0 = s; k0 = i; }
    else if (s < e1 || (s == e1 && i < k1)) { e1 = s; k1 = i; }
}

// ---- Kernel C: quad-parallel exact rescue + perplexity + replay-state reset ----
__global__ void vq_rescue_perp(const float* __restrict__ inputs,
                               const float* __restrict__ codebook,
                               float* __restrict__ out, int out_size) {
    const int n    = g_nflag;
    const int gw   = (blockIdx.x * blockDim.x + threadIdx.x) >> 5;
    const int lane = threadIdx.x & 31;
    const int nw   = (gridDim.x * blockDim.x) >> 5;
    const int j    = lane >> 2;          // candidate slot 0..7
    const int qq   = lane & 3;           // 16-dim quarter

    for (int i = gw; i < n; i += nw) {
        const int T = g_ftok[i];
        const uint4 cw = g_fcand[i];
        const unsigned cand2[4] = { cw.x, cw.y, cw.z, cw.w };
        const int k = (int)((cand2[j >> 1] >> ((j & 1) * 16)) & 0xffffu);
        const int b = T >> 12, hw = T & (HWSZ - 1);
        const float* xt = inputs + (b * D) * HWSZ + hw;

        float xs[16];
#pragma unroll
        for (int m = 0; m < 16; ++m) xs[m] = __ldg(&xt[(qq * 16 + m) * HWSZ]);
        const float4* cp = reinterpret_cast<const float4*>(codebook + k * D + qq * 16);
        float d0 = 0.f, d1 = 0.f, d2 = 0.f, d3 = 0.f;
#pragma unroll
        for (int w = 0; w < 4; ++w) {
            float4 cv = __ldg(&cp[w]);
            d0 = fmaf(xs[4 * w + 0], cv.x, d0);
            d1 = fmaf(xs[4 * w + 1], cv.y, d1);
            d2 = fmaf(xs[4 * w + 2], cv.z, d2);
            d3 = fmaf(xs[4 * w + 3], cv.w, d3);
        }
        float part = (d0 + d1) + (d2 + d3);
        part += __shfl_xor_sync(0xffffffffu, part, 1);
        part += __shfl_xor_sync(0xffffffffu, part, 2);
        float e = g_cnorm[k] - 2.0f * part;

        float e0 = e, e1 = 3.4e38f;
        int   k0 = k, k1 = 0x7fffffff;
#pragma unroll
        for (int d = 4; d <= 16; d <<= 1) {
            float re0 = __shfl_xor_sync(0xffffffffu, e0, d);
            float re1 = __shfl_xor_sync(0xffffffffu, e1, d);
            int   rk0 = __shfl_xor_sync(0xffffffffu, k0, d);
            int   rk1 = __shfl_xor_sync(0xffffffffu, k1, d);
            ins2f(re0, rk0, e0, k0, e1, k1);
            ins2f(re1, rk1, e0, k0, e1, k1);
        }

        int bestk = k0;
        float x0 = __ldg(&xt[(2 * lane) * HWSZ]);
        float x1 = __ldg(&xt[(2 * lane + 1) * HWSZ]);
        if (e1 - e0 < RESCUE) {                  // fp64 grid rescue (R2-proven)
            double A = wsumd((double)(x0 * x0) + (double)(x1 * x1));
            float A32 = (float)A;
            int klo = min(k0, k1), khi = max(k0, k1);
            float dsc[2];
#pragma unroll
            for (int jj = 0; jj < 2; ++jj) {
                int kk = jj ? khi : klo;
                float2 cv = *reinterpret_cast<const float2*>(codebook + kk * D + 2 * lane);
                double dot = wsumd((double)x0 * (double)cv.x + (double)x1 * (double)cv.y);
                double C   = wsumd((double)(cv.x * cv.x) + (double)(cv.y * cv.y));
                float t1 = (float)dot;
                float t2 = A32 - 2.0f * t1;
                dsc[jj] = t2 + (float)C;
            }
            bestk = (dsc[1] < dsc[0]) ? khi : klo;
        }
        if (lane == 0) atomicAdd(&g_counts[bestk], 1);
        float2 qv = *reinterpret_cast<const float2*>(codebook + bestk * D + 2 * lane);
        float* op = out + (b * D) * HWSZ + hw;
        op[(2 * lane) * HWSZ]     = x0 + (qv.x - x0);
        op[(2 * lane + 1) * HWSZ] = x1 + (qv.y - x1);
    }

    // Last CTA: perplexity from final counts, then reset replay state.
    __shared__ int sflag;
    __shared__ float red[8];
    __threadfence();
    __syncthreads();
    if (threadIdx.x == 0) sflag = (atomicAdd(&g_done, 1) == gridDim.x - 1);
    __syncthreads();
    if (!sflag) return;
    __threadfence();

    const int t = threadIdx.x;
    float v = 0.f;
#pragma unroll
    for (int jj = 0; jj < 4; ++jj) {
        float e = (float)g_counts[t * 4 + jj] * (1.0f / (float)NTOK);
        v += e * logf(e + 1e-10f);
    }
#pragma unroll
    for (int o = 16; o > 0; o >>= 1) v += __shfl_down_sync(0xffffffffu, v, o);
    if ((t & 31) == 0) red[t >> 5] = v;
    __syncthreads();
    if (t == 0) {
        float s = 0.f;
#pragma unroll
        for (int jj = 0; jj < 8; ++jj) s += red[jj];
        if (out_size > NTOK * D) out[NTOK * D] = expf(-s);
    }
    __syncthreads();
#pragma unroll
    for (int jj = 0; jj < 4; ++jj) g_counts[t * 4 + jj] = 0;
    if (t == 0) { g_nflag = 0; g_done = 0; }
}

extern "C" void kernel_launch(void* const* d_in, const int* in_sizes, int n_in,
                              void* d_out, int out_size) {
    const float* inputs   = (const float*)d_in[0];
    const float* codebook = (const float*)d_in[1];
    float*       out      = (float*)d_out;

    cudaFuncSetAttribute(vq_main, cudaFuncAttributeMaxDynamicSharedMemorySize, SM_TOTAL);

    vq_prep<<<KCODES / 8, TPB>>>(codebook);
    vq_main<<<NTOK / TOKS, TPB, SM_TOTAL>>>(inputs, codebook, out);
    vq_rescue_perp<<<RGRID, TPB>>>(inputs, codebook, out, out_size);
}